// round 3
// baseline (speedup 1.0000x reference)
#include <cuda_runtime.h>
#include <cstddef>

#define NA 100000
#define NB 100000
#define DD 64

// ---------------- scratch (device globals: no allocation allowed) ----------
__device__ float g_m0[NB * DD];
__device__ float g_m1[NA * DD];
__device__ float g_m2[NA * DD];
__device__ float g_c0[NB];
__device__ float g_c1[NA];
__device__ float g_c2[NA];
__device__ float g_A1[NA * DD];
__device__ float g_B1[NB * DD];

// ---------------- fused 3-type edge aggregation -----------------------------
// Grid is split into 3 contiguous per-type segments (type resolved once per
// block). 16 threads cooperate on one edge (one red.global.add.v4.f32 each);
// each thread handles 8 edges, with loads phase-batched for MLP~8.
template<bool COUNT>
__global__ void agg3_kernel(const float* __restrict__ xA,
                            const float* __restrict__ xB,
                            const int* __restrict__ src0, const int* __restrict__ dst0,
                            const int* __restrict__ src1, const int* __restrict__ dst1,
                            const int* __restrict__ src2, const int* __restrict__ dst2,
                            float* __restrict__ m0, float* __restrict__ m1,
                            float* __restrict__ m2,
                            float* __restrict__ c0, float* __restrict__ c1,
                            float* __restrict__ c2,
                            int nb0, int nb01,
                            int E0, int E1, int E2,
                            int C0, int C1, int C2) {
    int bid = blockIdx.x;
    const float* xs; const int* sp; const int* dp; float* mp; float* cp;
    int E, C, bloc;
    if (bid < nb0)       { bloc = bid;        xs = xA; sp = src0; dp = dst0; mp = m0; cp = c0; E = E0; C = C0; }
    else if (bid < nb01) { bloc = bid - nb0;  xs = xB; sp = src1; dp = dst1; mp = m1; cp = c1; E = E1; C = C1; }
    else                 { bloc = bid - nb01; xs = xA; sp = src2; dp = dst2; mp = m2; cp = c2; E = E2; C = C2; }

    int t = bloc * 256 + threadIdx.x;
    int eb = t >> 4;
    int c = t & 15;

    int s[8], d[8];
    bool ok[8];
#pragma unroll
    for (int j = 0; j < 8; j++) {
        int e = eb + j * C;
        ok[j] = (e < E);
        s[j] = ok[j] ? __ldg(sp + e) : 0;
        d[j] = ok[j] ? __ldg(dp + e) : 0;
    }
    float4 v[8];
#pragma unroll
    for (int j = 0; j < 8; j++)
        if (ok[j]) v[j] = __ldg((const float4*)xs + (size_t)s[j] * 16 + c);
#pragma unroll
    for (int j = 0; j < 8; j++) {
        if (ok[j]) {
            float* addr = mp + (size_t)d[j] * 64 + c * 4;
            asm volatile("red.global.add.v4.f32 [%0], {%1, %2, %3, %4};"
                         :: "l"(addr), "f"(v[j].x), "f"(v[j].y), "f"(v[j].z), "f"(v[j].w));
            if (COUNT && c == 0) atomicAdd(cp + d[j], 1.0f);
        }
    }
}

// ---------------- counts -> reciprocals (computed once, reused by layer 1) -
__global__ void recip_kernel() {
    int i = blockIdx.x * blockDim.x + threadIdx.x;
    if (i < NB) g_c0[i] = 1.0f / fmaxf(g_c0[i], 1.0f);
    if (i < NA) {
        g_c1[i] = 1.0f / fmaxf(g_c1[i], 1.0f);
        g_c2[i] = 1.0f / fmaxf(g_c2[i], 1.0f);
    }
}

// ---------------- fused combine (A-side combine3 + B-side combine2),
//                  optionally with the ReLU head fused on top ---------------
template<bool HEAD>
__global__ __launch_bounds__(256) void combine_kernel(
    const float* __restrict__ m0, const float* __restrict__ rc0,
    const float* __restrict__ m1, const float* __restrict__ rc1,
    const float* __restrict__ m2, const float* __restrict__ rc2,
    const float* __restrict__ xA, const float* __restrict__ xB,
    const float* __restrict__ Wn, const float* __restrict__ Wr,
    const float* __restrict__ bias,
    const float* __restrict__ Wout, const float* __restrict__ bout,
    float* __restrict__ outA, float* __restrict__ outB, int nbA) {
    __shared__ float4 sbuf[3 * 512];
    const int j = threadIdx.x & 63;
    const int rg = threadIdx.x >> 6;
    float h[8];
    float* outX;
    int row0;

    if (blockIdx.x < nbA) {
        // ---------- A side: mean(m1)@Wn1 + mean(m2)@Wn2 + x@(Wr1+Wr2) + b1+b2
        row0 = blockIdx.x * 32;
        outX = outA;
        float4* sm1 = sbuf;
        float4* sm2 = sbuf + 512;
        float4* smx = sbuf + 1024;
        for (int i = threadIdx.x; i < 512; i += 256) {
            int r = i >> 4;
            int c4 = i & 15;
            float i1 = __ldg(rc1 + row0 + r);
            float i2 = __ldg(rc2 + row0 + r);
            float4 v1 = __ldg((const float4*)m1 + (size_t)(row0 + r) * 16 + c4);
            float4 v2 = __ldg((const float4*)m2 + (size_t)(row0 + r) * 16 + c4);
            v1.x *= i1; v1.y *= i1; v1.z *= i1; v1.w *= i1;
            v2.x *= i2; v2.y *= i2; v2.z *= i2; v2.w *= i2;
            sm1[i] = v1;
            sm2[i] = v2;
            smx[i] = __ldg((const float4*)xA + (size_t)(row0 + r) * 16 + c4);
        }
        float wn1[64], wn2[64], wrs[64];
#pragma unroll
        for (int k = 0; k < 64; k++) {
            wn1[k] = __ldg(Wn + 1 * 4096 + k * 64 + j);
            wn2[k] = __ldg(Wn + 2 * 4096 + k * 64 + j);
            wrs[k] = __ldg(Wr + 1 * 4096 + k * 64 + j) + __ldg(Wr + 2 * 4096 + k * 64 + j);
        }
        float bj = __ldg(bias + 1 * 64 + j) + __ldg(bias + 2 * 64 + j);
        __syncthreads();
#pragma unroll
        for (int rr = 0; rr < 8; rr++) {
            int r = rg * 8 + rr;
            const float4* p1 = sm1 + r * 16;
            const float4* p2 = sm2 + r * 16;
            const float4* px = smx + r * 16;
            float a0 = bj, a1 = 0.f;
#pragma unroll
            for (int k4 = 0; k4 < 8; k4++) {
                float4 a = p1[k4];
                a0 += a.x * wn1[4 * k4 + 0] + a.y * wn1[4 * k4 + 1]
                    + a.z * wn1[4 * k4 + 2] + a.w * wn1[4 * k4 + 3];
                float4 b = p2[k4];
                a0 += b.x * wn2[4 * k4 + 0] + b.y * wn2[4 * k4 + 1]
                    + b.z * wn2[4 * k4 + 2] + b.w * wn2[4 * k4 + 3];
                float4 cc = px[k4];
                a0 += cc.x * wrs[4 * k4 + 0] + cc.y * wrs[4 * k4 + 1]
                    + cc.z * wrs[4 * k4 + 2] + cc.w * wrs[4 * k4 + 3];
            }
#pragma unroll
            for (int k4 = 8; k4 < 16; k4++) {
                float4 a = p1[k4];
                a1 += a.x * wn1[4 * k4 + 0] + a.y * wn1[4 * k4 + 1]
                    + a.z * wn1[4 * k4 + 2] + a.w * wn1[4 * k4 + 3];
                float4 b = p2[k4];
                a1 += b.x * wn2[4 * k4 + 0] + b.y * wn2[4 * k4 + 1]
                    + b.z * wn2[4 * k4 + 2] + b.w * wn2[4 * k4 + 3];
                float4 cc = px[k4];
                a1 += cc.x * wrs[4 * k4 + 0] + cc.y * wrs[4 * k4 + 1]
                    + cc.z * wrs[4 * k4 + 2] + cc.w * wrs[4 * k4 + 3];
            }
            h[rr] = a0 + a1;
        }
    } else {
        // ---------- B side: mean(m0)@Wn0 + x@Wr0 + b0
        row0 = (blockIdx.x - nbA) * 32;
        outX = outB;
        float4* smm = sbuf;
        float4* smx = sbuf + 1024;
        for (int i = threadIdx.x; i < 512; i += 256) {
            int r = i >> 4;
            int c4 = i & 15;
            float iv = __ldg(rc0 + row0 + r);
            float4 v = __ldg((const float4*)m0 + (size_t)(row0 + r) * 16 + c4);
            v.x *= iv; v.y *= iv; v.z *= iv; v.w *= iv;
            smm[i] = v;
            smx[i] = __ldg((const float4*)xB + (size_t)(row0 + r) * 16 + c4);
        }
        float wn[64], wr[64];
#pragma unroll
        for (int k = 0; k < 64; k++) {
            wn[k] = __ldg(Wn + k * 64 + j);
            wr[k] = __ldg(Wr + k * 64 + j);
        }
        float bj = __ldg(bias + j);
        __syncthreads();
#pragma unroll
        for (int rr = 0; rr < 8; rr++) {
            int r = rg * 8 + rr;
            const float4* pm = smm + r * 16;
            const float4* px = smx + r * 16;
            float a0 = bj, a1 = 0.f;
#pragma unroll
            for (int k4 = 0; k4 < 8; k4++) {
                float4 a = pm[k4];
                a0 += a.x * wn[4 * k4 + 0] + a.y * wn[4 * k4 + 1]
                    + a.z * wn[4 * k4 + 2] + a.w * wn[4 * k4 + 3];
                float4 bv = px[k4];
                a0 += bv.x * wr[4 * k4 + 0] + bv.y * wr[4 * k4 + 1]
                    + bv.z * wr[4 * k4 + 2] + bv.w * wr[4 * k4 + 3];
            }
#pragma unroll
            for (int k4 = 8; k4 < 16; k4++) {
                float4 a = pm[k4];
                a1 += a.x * wn[4 * k4 + 0] + a.y * wn[4 * k4 + 1]
                    + a.z * wn[4 * k4 + 2] + a.w * wn[4 * k4 + 3];
                float4 bv = px[k4];
                a1 += bv.x * wr[4 * k4 + 0] + bv.y * wr[4 * k4 + 1]
                    + bv.z * wr[4 * k4 + 2] + bv.w * wr[4 * k4 + 3];
            }
            h[rr] = a0 + a1;
        }
    }

    if (!HEAD) {
#pragma unroll
        for (int rr = 0; rr < 8; rr++)
            outX[(size_t)(row0 + rg * 8 + rr) * 64 + j] = h[rr];
    } else {
        // ---------- fused head: out = relu(h @ Wout + bout), h staged in smem
        __syncthreads();                       // all phase-1 smem reads done
        float* hb = (float*)sbuf;              // reuse first 8KB as h[32][64]
#pragma unroll
        for (int rr = 0; rr < 8; rr++)
            hb[(rg * 8 + rr) * 64 + j] = h[rr];
        float w[64];
#pragma unroll
        for (int k = 0; k < 64; k++) w[k] = __ldg(Wout + k * 64 + j);
        float bj2 = __ldg(bout + j);
        __syncthreads();
#pragma unroll
        for (int rr = 0; rr < 8; rr++) {
            int r = rg * 8 + rr;
            const float4* ph = (const float4*)(hb + r * 64);
            float a0 = bj2, a1 = 0.f;
#pragma unroll
            for (int k4 = 0; k4 < 8; k4++) {
                float4 cc = ph[k4];
                a0 += cc.x * w[4 * k4 + 0] + cc.y * w[4 * k4 + 1]
                    + cc.z * w[4 * k4 + 2] + cc.w * w[4 * k4 + 3];
            }
#pragma unroll
            for (int k4 = 8; k4 < 16; k4++) {
                float4 cc = ph[k4];
                a1 += cc.x * w[4 * k4 + 0] + cc.y * w[4 * k4 + 1]
                    + cc.z * w[4 * k4 + 2] + cc.w * w[4 * k4 + 3];
            }
            outX[(size_t)(row0 + r) * 64 + j] = fmaxf(a0 + a1, 0.0f);
        }
    }
}

// ---------------- launcher --------------------------------------------------
extern "C" void kernel_launch(void* const* d_in, const int* in_sizes, int n_in,
                              void* d_out, int out_size) {
    const float* x_A   = (const float*)d_in[0];
    const float* x_B   = (const float*)d_in[1];
    const float* Wn    = (const float*)d_in[2];   // [2,3,64,64]
    const float* Wr    = (const float*)d_in[3];   // [2,3,64,64]
    const float* b     = (const float*)d_in[4];   // [2,3,64]
    const float* W_out = (const float*)d_in[5];   // [64,64]
    const float* b_out = (const float*)d_in[6];   // [64]
    const int* src0 = (const int*)d_in[7];
    const int* dst0 = (const int*)d_in[8];
    const int* src1 = (const int*)d_in[9];
    const int* dst1 = (const int*)d_in[10];
    const int* src2 = (const int*)d_in[11];
    const int* dst2 = (const int*)d_in[12];
    const int E0 = in_sizes[7];
    const int E1 = in_sizes[9];
    const int E2 = in_sizes[11];
    float* out = (float*)d_out;

    float *m0, *m1, *m2, *c0, *c1, *c2, *A1, *B1;
    cudaGetSymbolAddress((void**)&m0, g_m0);
    cudaGetSymbolAddress((void**)&m1, g_m1);
    cudaGetSymbolAddress((void**)&m2, g_m2);
    cudaGetSymbolAddress((void**)&c0, g_c0);
    cudaGetSymbolAddress((void**)&c1, g_c1);
    cudaGetSymbolAddress((void**)&c2, g_c2);
    cudaGetSymbolAddress((void**)&A1, g_A1);
    cudaGetSymbolAddress((void**)&B1, g_B1);

    // per-type segment sizes: C = ceil(E/8) edge-groups, 16 threads per group
    const int Cc0 = (E0 + 7) / 8, Cc1 = (E1 + 7) / 8, Cc2 = (E2 + 7) / 8;
    const int nb0 = (int)(((long long)Cc0 * 16 + 255) / 256);
    const int nb1 = (int)(((long long)Cc1 * 16 + 255) / 256);
    const int nb2 = (int)(((long long)Cc2 * 16 + 255) / 256);
    const int aggBlocks = nb0 + nb1 + nb2;
    const int nbA = NA / 32;  // 3125
    const int nbB = NB / 32;  // 3125
    const size_t mbytes = (size_t)NA * DD * sizeof(float);

    // ---- layer 0 ----
    cudaMemsetAsync(m0, 0, mbytes);
    cudaMemsetAsync(m1, 0, mbytes);
    cudaMemsetAsync(m2, 0, mbytes);
    cudaMemsetAsync(c0, 0, NB * sizeof(float));
    cudaMemsetAsync(c1, 0, NA * sizeof(float));
    cudaMemsetAsync(c2, 0, NA * sizeof(float));
    agg3_kernel<true><<<aggBlocks, 256>>>(x_A, x_B, src0, dst0, src1, dst1,
                                          src2, dst2, m0, m1, m2, c0, c1, c2,
                                          nb0, nb0 + nb1,
                                          E0, E1, E2, Cc0, Cc1, Cc2);
    recip_kernel<<<(NA + 255) / 256, 256>>>();
    combine_kernel<false><<<nbA + nbB, 256>>>(m0, c0, m1, c1, m2, c2,
                                              x_A, x_B,
                                              Wn, Wr, b,
                                              nullptr, nullptr,
                                              A1, B1, nbA);

    // ---- layer 1 (counts/reciprocals reused: dst arrays unchanged) ----
    cudaMemsetAsync(m0, 0, mbytes);
    cudaMemsetAsync(m1, 0, mbytes);
    cudaMemsetAsync(m2, 0, mbytes);
    agg3_kernel<false><<<aggBlocks, 256>>>(A1, B1, src0, dst0, src1, dst1,
                                           src2, dst2, m0, m1, m2, c0, c1, c2,
                                           nb0, nb0 + nb1,
                                           E0, E1, E2, Cc0, Cc1, Cc2);
    combine_kernel<true><<<nbA + nbB, 256>>>(m0, c0, m1, c1, m2, c2,
                                             A1, B1,
                                             Wn + 3 * 4096, Wr + 3 * 4096, b + 3 * 64,
                                             W_out, b_out,
                                             out, out + (size_t)NA * 64, nbA);
}

// round 4
// speedup vs baseline: 1.0971x; 1.0971x over previous
#include <cuda_runtime.h>
#include <cstddef>

#define NA 100000
#define NB 100000
#define DD 64

// ---------------- scratch (device globals: no allocation allowed) ----------
__device__ float g_m0[NB * DD];
__device__ float g_m1[NA * DD];
__device__ float g_m2[NA * DD];
__device__ float g_c0[NB];
__device__ float g_c1[NA];
__device__ float g_c2[NA];
__device__ float g_A1[NA * DD];
__device__ float g_B1[NB * DD];

// ---------------- fused 3-type edge aggregation -----------------------------
// Grid split into 3 contiguous per-type segments (type resolved once per
// block -> per-phase working set ~51MB, L2-resident). 16 threads cooperate on
// one edge (one red.global.add.v4.f32 each); each thread handles 4 edges with
// phase-batched loads (MLP~4) while keeping regs low enough for high occupancy.
template<bool COUNT>
__global__ __launch_bounds__(256, 6)
void agg3_kernel(const float* __restrict__ xA,
                 const float* __restrict__ xB,
                 const int* __restrict__ src0, const int* __restrict__ dst0,
                 const int* __restrict__ src1, const int* __restrict__ dst1,
                 const int* __restrict__ src2, const int* __restrict__ dst2,
                 float* __restrict__ m0, float* __restrict__ m1,
                 float* __restrict__ m2,
                 float* __restrict__ c0, float* __restrict__ c1,
                 float* __restrict__ c2,
                 int nb0, int nb01,
                 int E0, int E1, int E2,
                 int C0, int C1, int C2) {
    int bid = blockIdx.x;
    const float* xs; const int* sp; const int* dp; float* mp; float* cp;
    int E, C, bloc;
    if (bid < nb0)       { bloc = bid;        xs = xA; sp = src0; dp = dst0; mp = m0; cp = c0; E = E0; C = C0; }
    else if (bid < nb01) { bloc = bid - nb0;  xs = xB; sp = src1; dp = dst1; mp = m1; cp = c1; E = E1; C = C1; }
    else                 { bloc = bid - nb01; xs = xA; sp = src2; dp = dst2; mp = m2; cp = c2; E = E2; C = C2; }

    int t = bloc * 256 + threadIdx.x;
    int eb = t >> 4;
    int c = t & 15;

    int s[4], d[4];
    bool ok[4];
#pragma unroll
    for (int j = 0; j < 4; j++) {
        int e = eb + j * C;
        ok[j] = (e < E);
        s[j] = ok[j] ? __ldg(sp + e) : 0;
        d[j] = ok[j] ? __ldg(dp + e) : 0;
    }
    float4 v[4];
#pragma unroll
    for (int j = 0; j < 4; j++)
        if (ok[j]) v[j] = __ldg((const float4*)xs + (size_t)s[j] * 16 + c);
#pragma unroll
    for (int j = 0; j < 4; j++) {
        if (ok[j]) {
            float* addr = mp + (size_t)d[j] * 64 + c * 4;
            asm volatile("red.global.add.v4.f32 [%0], {%1, %2, %3, %4};"
                         :: "l"(addr), "f"(v[j].x), "f"(v[j].y), "f"(v[j].z), "f"(v[j].w));
            if (COUNT && c == 0) atomicAdd(cp + d[j], 1.0f);
        }
    }
}

// ---------------- counts -> reciprocals (computed once, reused by layer 1) -
__global__ void recip_kernel() {
    int i = blockIdx.x * blockDim.x + threadIdx.x;
    if (i < NB) g_c0[i] = 1.0f / fmaxf(g_c0[i], 1.0f);
    if (i < NA) {
        g_c1[i] = 1.0f / fmaxf(g_c1[i], 1.0f);
        g_c2[i] = 1.0f / fmaxf(g_c2[i], 1.0f);
    }
}

// ---------------- fused combine (A-side combine3 + B-side combine2),
//                  optionally with the ReLU head fused on top ---------------
template<bool HEAD>
__global__ __launch_bounds__(256) void combine_kernel(
    const float* __restrict__ m0, const float* __restrict__ rc0,
    const float* __restrict__ m1, const float* __restrict__ rc1,
    const float* __restrict__ m2, const float* __restrict__ rc2,
    const float* __restrict__ xA, const float* __restrict__ xB,
    const float* __restrict__ Wn, const float* __restrict__ Wr,
    const float* __restrict__ bias,
    const float* __restrict__ Wout, const float* __restrict__ bout,
    float* __restrict__ outA, float* __restrict__ outB, int nbA) {
    __shared__ float4 sbuf[3 * 512];
    const int j = threadIdx.x & 63;
    const int rg = threadIdx.x >> 6;
    float h[8];
    float* outX;
    int row0;

    if (blockIdx.x < nbA) {
        // ---------- A side: mean(m1)@Wn1 + mean(m2)@Wn2 + x@(Wr1+Wr2) + b1+b2
        row0 = blockIdx.x * 32;
        outX = outA;
        float4* sm1 = sbuf;
        float4* sm2 = sbuf + 512;
        float4* smx = sbuf + 1024;
        for (int i = threadIdx.x; i < 512; i += 256) {
            int r = i >> 4;
            int c4 = i & 15;
            float i1 = __ldg(rc1 + row0 + r);
            float i2 = __ldg(rc2 + row0 + r);
            float4 v1 = __ldg((const float4*)m1 + (size_t)(row0 + r) * 16 + c4);
            float4 v2 = __ldg((const float4*)m2 + (size_t)(row0 + r) * 16 + c4);
            v1.x *= i1; v1.y *= i1; v1.z *= i1; v1.w *= i1;
            v2.x *= i2; v2.y *= i2; v2.z *= i2; v2.w *= i2;
            sm1[i] = v1;
            sm2[i] = v2;
            smx[i] = __ldg((const float4*)xA + (size_t)(row0 + r) * 16 + c4);
        }
        float wn1[64], wn2[64], wrs[64];
#pragma unroll
        for (int k = 0; k < 64; k++) {
            wn1[k] = __ldg(Wn + 1 * 4096 + k * 64 + j);
            wn2[k] = __ldg(Wn + 2 * 4096 + k * 64 + j);
            wrs[k] = __ldg(Wr + 1 * 4096 + k * 64 + j) + __ldg(Wr + 2 * 4096 + k * 64 + j);
        }
        float bj = __ldg(bias + 1 * 64 + j) + __ldg(bias + 2 * 64 + j);
        __syncthreads();
#pragma unroll
        for (int rr = 0; rr < 8; rr++) {
            int r = rg * 8 + rr;
            const float4* p1 = sm1 + r * 16;
            const float4* p2 = sm2 + r * 16;
            const float4* px = smx + r * 16;
            float a0 = bj, a1 = 0.f;
#pragma unroll
            for (int k4 = 0; k4 < 8; k4++) {
                float4 a = p1[k4];
                a0 += a.x * wn1[4 * k4 + 0] + a.y * wn1[4 * k4 + 1]
                    + a.z * wn1[4 * k4 + 2] + a.w * wn1[4 * k4 + 3];
                float4 b = p2[k4];
                a0 += b.x * wn2[4 * k4 + 0] + b.y * wn2[4 * k4 + 1]
                    + b.z * wn2[4 * k4 + 2] + b.w * wn2[4 * k4 + 3];
                float4 cc = px[k4];
                a0 += cc.x * wrs[4 * k4 + 0] + cc.y * wrs[4 * k4 + 1]
                    + cc.z * wrs[4 * k4 + 2] + cc.w * wrs[4 * k4 + 3];
            }
#pragma unroll
            for (int k4 = 8; k4 < 16; k4++) {
                float4 a = p1[k4];
                a1 += a.x * wn1[4 * k4 + 0] + a.y * wn1[4 * k4 + 1]
                    + a.z * wn1[4 * k4 + 2] + a.w * wn1[4 * k4 + 3];
                float4 b = p2[k4];
                a1 += b.x * wn2[4 * k4 + 0] + b.y * wn2[4 * k4 + 1]
                    + b.z * wn2[4 * k4 + 2] + b.w * wn2[4 * k4 + 3];
                float4 cc = px[k4];
                a1 += cc.x * wrs[4 * k4 + 0] + cc.y * wrs[4 * k4 + 1]
                    + cc.z * wrs[4 * k4 + 2] + cc.w * wrs[4 * k4 + 3];
            }
            h[rr] = a0 + a1;
        }
    } else {
        // ---------- B side: mean(m0)@Wn0 + x@Wr0 + b0
        row0 = (blockIdx.x - nbA) * 32;
        outX = outB;
        float4* smm = sbuf;
        float4* smx = sbuf + 1024;
        for (int i = threadIdx.x; i < 512; i += 256) {
            int r = i >> 4;
            int c4 = i & 15;
            float iv = __ldg(rc0 + row0 + r);
            float4 v = __ldg((const float4*)m0 + (size_t)(row0 + r) * 16 + c4);
            v.x *= iv; v.y *= iv; v.z *= iv; v.w *= iv;
            smm[i] = v;
            smx[i] = __ldg((const float4*)xB + (size_t)(row0 + r) * 16 + c4);
        }
        float wn[64], wr[64];
#pragma unroll
        for (int k = 0; k < 64; k++) {
            wn[k] = __ldg(Wn + k * 64 + j);
            wr[k] = __ldg(Wr + k * 64 + j);
        }
        float bj = __ldg(bias + j);
        __syncthreads();
#pragma unroll
        for (int rr = 0; rr < 8; rr++) {
            int r = rg * 8 + rr;
            const float4* pm = smm + r * 16;
            const float4* px = smx + r * 16;
            float a0 = bj, a1 = 0.f;
#pragma unroll
            for (int k4 = 0; k4 < 8; k4++) {
                float4 a = pm[k4];
                a0 += a.x * wn[4 * k4 + 0] + a.y * wn[4 * k4 + 1]
                    + a.z * wn[4 * k4 + 2] + a.w * wn[4 * k4 + 3];
                float4 bv = px[k4];
                a0 += bv.x * wr[4 * k4 + 0] + bv.y * wr[4 * k4 + 1]
                    + bv.z * wr[4 * k4 + 2] + bv.w * wr[4 * k4 + 3];
            }
#pragma unroll
            for (int k4 = 8; k4 < 16; k4++) {
                float4 a = pm[k4];
                a1 += a.x * wn[4 * k4 + 0] + a.y * wn[4 * k4 + 1]
                    + a.z * wn[4 * k4 + 2] + a.w * wn[4 * k4 + 3];
                float4 bv = px[k4];
                a1 += bv.x * wr[4 * k4 + 0] + bv.y * wr[4 * k4 + 1]
                    + bv.z * wr[4 * k4 + 2] + bv.w * wr[4 * k4 + 3];
            }
            h[rr] = a0 + a1;
        }
    }

    if (!HEAD) {
#pragma unroll
        for (int rr = 0; rr < 8; rr++)
            outX[(size_t)(row0 + rg * 8 + rr) * 64 + j] = h[rr];
    } else {
        // ---------- fused head: out = relu(h @ Wout + bout), h staged in smem
        __syncthreads();                       // all phase-1 smem reads done
        float* hb = (float*)sbuf;              // reuse first 8KB as h[32][64]
#pragma unroll
        for (int rr = 0; rr < 8; rr++)
            hb[(rg * 8 + rr) * 64 + j] = h[rr];
        float w[64];
#pragma unroll
        for (int k = 0; k < 64; k++) w[k] = __ldg(Wout + k * 64 + j);
        float bj2 = __ldg(bout + j);
        __syncthreads();
#pragma unroll
        for (int rr = 0; rr < 8; rr++) {
            int r = rg * 8 + rr;
            const float4* ph = (const float4*)(hb + r * 64);
            float a0 = bj2, a1 = 0.f;
#pragma unroll
            for (int k4 = 0; k4 < 8; k4++) {
                float4 cc = ph[k4];
                a0 += cc.x * w[4 * k4 + 0] + cc.y * w[4 * k4 + 1]
                    + cc.z * w[4 * k4 + 2] + cc.w * w[4 * k4 + 3];
            }
#pragma unroll
            for (int k4 = 8; k4 < 16; k4++) {
                float4 cc = ph[k4];
                a1 += cc.x * w[4 * k4 + 0] + cc.y * w[4 * k4 + 1]
                    + cc.z * w[4 * k4 + 2] + cc.w * w[4 * k4 + 3];
            }
            outX[(size_t)(row0 + r) * 64 + j] = fmaxf(a0 + a1, 0.0f);
        }
    }
}

// ---------------- launcher --------------------------------------------------
extern "C" void kernel_launch(void* const* d_in, const int* in_sizes, int n_in,
                              void* d_out, int out_size) {
    const float* x_A   = (const float*)d_in[0];
    const float* x_B   = (const float*)d_in[1];
    const float* Wn    = (const float*)d_in[2];   // [2,3,64,64]
    const float* Wr    = (const float*)d_in[3];   // [2,3,64,64]
    const float* b     = (const float*)d_in[4];   // [2,3,64]
    const float* W_out = (const float*)d_in[5];   // [64,64]
    const float* b_out = (const float*)d_in[6];   // [64]
    const int* src0 = (const int*)d_in[7];
    const int* dst0 = (const int*)d_in[8];
    const int* src1 = (const int*)d_in[9];
    const int* dst1 = (const int*)d_in[10];
    const int* src2 = (const int*)d_in[11];
    const int* dst2 = (const int*)d_in[12];
    const int E0 = in_sizes[7];
    const int E1 = in_sizes[9];
    const int E2 = in_sizes[11];
    float* out = (float*)d_out;

    float *m0, *m1, *m2, *c0, *c1, *c2, *A1, *B1;
    cudaGetSymbolAddress((void**)&m0, g_m0);
    cudaGetSymbolAddress((void**)&m1, g_m1);
    cudaGetSymbolAddress((void**)&m2, g_m2);
    cudaGetSymbolAddress((void**)&c0, g_c0);
    cudaGetSymbolAddress((void**)&c1, g_c1);
    cudaGetSymbolAddress((void**)&c2, g_c2);
    cudaGetSymbolAddress((void**)&A1, g_A1);
    cudaGetSymbolAddress((void**)&B1, g_B1);

    // per-type segment sizes: C = ceil(E/4) edge-groups, 16 threads per group
    const int Cc0 = (E0 + 3) / 4, Cc1 = (E1 + 3) / 4, Cc2 = (E2 + 3) / 4;
    const int nb0 = (int)(((long long)Cc0 * 16 + 255) / 256);
    const int nb1 = (int)(((long long)Cc1 * 16 + 255) / 256);
    const int nb2 = (int)(((long long)Cc2 * 16 + 255) / 256);
    const int aggBlocks = nb0 + nb1 + nb2;
    const int nbA = NA / 32;  // 3125
    const int nbB = NB / 32;  // 3125
    const size_t mbytes = (size_t)NA * DD * sizeof(float);

    // ---- layer 0 ----
    cudaMemsetAsync(m0, 0, mbytes);
    cudaMemsetAsync(m1, 0, mbytes);
    cudaMemsetAsync(m2, 0, mbytes);
    cudaMemsetAsync(c0, 0, NB * sizeof(float));
    cudaMemsetAsync(c1, 0, NA * sizeof(float));
    cudaMemsetAsync(c2, 0, NA * sizeof(float));
    agg3_kernel<true><<<aggBlocks, 256>>>(x_A, x_B, src0, dst0, src1, dst1,
                                          src2, dst2, m0, m1, m2, c0, c1, c2,
                                          nb0, nb0 + nb1,
                                          E0, E1, E2, Cc0, Cc1, Cc2);
    recip_kernel<<<(NA + 255) / 256, 256>>>();
    combine_kernel<false><<<nbA + nbB, 256>>>(m0, c0, m1, c1, m2, c2,
                                              x_A, x_B,
                                              Wn, Wr, b,
                                              nullptr, nullptr,
                                              A1, B1, nbA);

    // ---- layer 1 (counts/reciprocals reused: dst arrays unchanged) ----
    cudaMemsetAsync(m0, 0, mbytes);
    cudaMemsetAsync(m1, 0, mbytes);
    cudaMemsetAsync(m2, 0, mbytes);
    agg3_kernel<false><<<aggBlocks, 256>>>(A1, B1, src0, dst0, src1, dst1,
                                           src2, dst2, m0, m1, m2, c0, c1, c2,
                                           nb0, nb0 + nb1,
                                           E0, E1, E2, Cc0, Cc1, Cc2);
    combine_kernel<true><<<nbA + nbB, 256>>>(m0, c0, m1, c1, m2, c2,
                                             A1, B1,
                                             Wn + 3 * 4096, Wr + 3 * 4096, b + 3 * 64,
                                             W_out, b_out,
                                             out, out + (size_t)NA * 64, nbA);
}